// round 6
// baseline (speedup 1.0000x reference)
#include <cuda_runtime.h>
#include <cuda_bf16.h>
#include <math.h>

#define IH 1024
#define IW 1024
#define NB 8
#define TW 32
#define TH 64
#define SIW 40   // s_img row stride (floats)
#define SW  36   // s_sx/s_sy/s_gm/s_t row stride

// tan((2k+1)*pi/16)
#define T0 0.1989123673796580f
#define T1 0.6681786379192989f
#define T2 1.4966057626654890f
#define T3 5.0273394921258481f
#define INV3 0.3333333333333333f

__device__ __forceinline__ int quant_q(float sx, float sy) {
    float ax = fabsf(sx), ay = fabsf(sy);
    int mm = (int)(ay > T0 * ax) + (int)(ay > T1 * ax)
           + (int)(ay > T2 * ax) + (int)(ay > T3 * ax);
    int neg = (__float_as_int(sx) ^ __float_as_int(sy)) < 0;
    return neg ? 4 - mm : 4 + mm;
}

__device__ __forceinline__ void ld8(const float* __restrict__ p, float* v) {
    float4 a = *(const float4*)p;
    float4 b = *(const float4*)(p + 4);
    v[0]=a.x; v[1]=a.y; v[2]=a.z; v[3]=a.w;
    v[4]=b.x; v[5]=b.y; v[6]=b.z; v[7]=b.w;
}

// ======================= interior (vectorized) =======================
__device__ __forceinline__ void body_int(
    const float* __restrict__ imgb, float* __restrict__ out,
    int b, int x0, int y0, int tid,
    float* __restrict__ s_img,   // 70*40; reused as s_t (66*36) after P2
    float* __restrict__ s_sx, float* __restrict__ s_sy, float* __restrict__ s_gm)
{
    // ---- P1: channel-summed image, rows 0..69 x cols 0..39 (gx = x0-4+c, gy = y0-3+r)
    {
        const float4* base = (const float4*)(imgb + (size_t)(y0 - 3) * IW + (x0 - 4));
        const int CH4 = IH * IW / 4;
        #pragma unroll
        for (int p = 0; p < 3; p++) {
            int idx = tid + 256 * p;
            if (idx < 700) {
                int r = idx / 10, c4 = idx % 10;
                const float4* ptr = base + r * (IW / 4) + c4;
                float4 v0 = ptr[0], v1 = ptr[CH4], v2 = ptr[2 * CH4];
                float4 s;
                s.x = v0.x + v1.x + v2.x; s.y = v0.y + v1.y + v2.y;
                s.z = v0.z + v1.z + v2.z; s.w = v0.w + v1.w + v2.w;
                *(float4*)&s_img[r * SIW + c4 * 4] = s;
            }
        }
    }
    __syncthreads();

    // ---- P2: sobel, rows 0..67 x col-groups 0..8 (cols 4g..4g+3). 612 tasks.
    #pragma unroll
    for (int p = 0; p < 3; p++) {
        int idx = tid + 256 * p;
        if (idx < 612) {
            int r = idx / 9, c = 4 * (idx % 9);
            float A[8], B[8], C[8];
            ld8(&s_img[r * SIW + c], A);
            ld8(&s_img[(r + 1) * SIW + c], B);
            ld8(&s_img[(r + 2) * SIW + c], C);
            float ox[4], oy[4], og[4];
            #pragma unroll
            for (int j = 0; j < 4; j++) {
                float u0 = A[j+3] - A[j+1], v0 = 0.5f * (A[j+1] + A[j+3]) + A[j+2];
                float u1 = B[j+3] - B[j+1];
                float u2 = C[j+3] - C[j+1], v2 = 0.5f * (C[j+1] + C[j+3]) + C[j+2];
                float sx = (0.5f * (u0 + u2) + u1) * INV3;
                float sy = (v2 - v0) * INV3;
                ox[j] = sx; oy[j] = sy; og[j] = sqrtf(sx * sx + sy * sy);
            }
            *(float4*)&s_sx[r * SW + c] = make_float4(ox[0], ox[1], ox[2], ox[3]);
            *(float4*)&s_sy[r * SW + c] = make_float4(oy[0], oy[1], oy[2], oy[3]);
            *(float4*)&s_gm[r * SW + c] = make_float4(og[0], og[1], og[2], og[3]);
        }
    }
    __syncthreads();

    // ---- P3: quant + NMS -> t, rows 0..65 x col-groups 0..8. 594 tasks.
    // t[r][c] valid for c<=33 (cols 34,35 garbage, never read).
    // NOTE: last row/last group ld8 reads run 4 floats past row end -> arrays padded +8.
    float* s_t = s_img;   // s_img dead now
    #pragma unroll
    for (int p = 0; p < 3; p++) {
        int idx = tid + 256 * p;
        if (idx < 594) {
            int r = idx / 9, c = 4 * (idx % 9);
            float g0[8], g1[8], g2[8], xs[8], ys[8];
            ld8(&s_gm[r * SW + c], g0);
            ld8(&s_gm[(r + 1) * SW + c], g1);
            ld8(&s_gm[(r + 2) * SW + c], g2);
            ld8(&s_sx[(r + 1) * SW + c], xs);
            ld8(&s_sy[(r + 1) * SW + c], ys);
            float tq[4];
            #pragma unroll
            for (int j = 0; j < 4; j++) {
                float gmc = g1[j + 1];
                int q = quant_q(xs[j + 1], ys[j + 1]);
                int k = q & 3;   // offs (0,1)(-1,1)(-1,0)(-1,-1)
                float mx0 = fmaxf(g1[j],     g1[j + 2]);
                float mx1 = fmaxf(g0[j + 2], g2[j]);
                float mx2 = fmaxf(g0[j + 1], g2[j + 1]);
                float mx3 = fmaxf(g0[j],     g2[j + 2]);
                float mxa = (k & 1) ? mx1 : mx0;
                float mxb = (k & 1) ? mx3 : mx2;
                float mx  = (k & 2) ? mxb : mxa;
                float thin = (gmc > mx) ? gmc : 0.0f;
                tq[j] = (thin > 0.5f ? 0.5f : 0.0f) + (thin > 1.0f ? 0.5f : 0.0f);
            }
            *(float4*)&s_t[r * SW + c] = make_float4(tq[0], tq[1], tq[2], tq[3]);
        }
    }
    __syncthreads();

    // ---- P4: hysteresis + 5-plane output, rows 0..63 x col-groups 0..7. 512 tasks.
    const size_t plane = (size_t)NB * IH * IW;
    float* o_gx = out;
    float* o_gy = out + plane;
    float* o_gm = out + 2 * plane;
    float* o_or = out + 3 * plane;
    float* o_te = out + 4 * plane;
    #pragma unroll
    for (int p = 0; p < 2; p++) {
        int idx = tid + 256 * p;
        int iy = idx >> 3, c = 4 * (idx & 7);
        float t0[8], t1[8], t2[8], xs[8], ys[8], gs[8];
        ld8(&s_t[iy * SW + c], t0);
        ld8(&s_t[(iy + 1) * SW + c], t1);
        ld8(&s_t[(iy + 2) * SW + c], t2);
        ld8(&s_sx[(iy + 2) * SW + c], xs);
        ld8(&s_sy[(iy + 2) * SW + c], ys);
        ld8(&s_gm[(iy + 2) * SW + c], gs);
        float vx[4], vy[4], vg[4], vo[4], ve[4];
        #pragma unroll
        for (int j = 0; j < 4; j++) {
            float rs0 = (t0[j] + t0[j + 1]) + t0[j + 2];
            float rs1 = (t1[j] + t1[j + 1]) + t1[j + 2];
            float rs2 = (t2[j] + t2[j + 1]) + t2[j + 2];
            float sum = (rs0 + rs1) + rs2;
            float tc  = t1[j + 1];
            float sx = xs[j + 2], sy = ys[j + 2];
            int q = quant_q(sx, sy);
            float qv = (float)q * 45.0f;
            if (sx == 0.0f && sy == 0.0f) qv = __int_as_float(0x7fc00000);
            float high = (tc == 1.0f) ? 1.0f : 0.0f;
            float weak = ((sum * 1.25f > 1.0f) && (tc == 0.5f)) ? 1.0f : 0.0f;
            vx[j] = sx; vy[j] = sy; vg[j] = gs[j + 2]; vo[j] = qv; ve[j] = high + weak;
        }
        size_t o = (size_t)b * IH * IW + (size_t)(y0 + iy) * IW + (x0 + c);
        __stcs((float4*)(o_gx + o), make_float4(vx[0], vx[1], vx[2], vx[3]));
        __stcs((float4*)(o_gy + o), make_float4(vy[0], vy[1], vy[2], vy[3]));
        __stcs((float4*)(o_gm + o), make_float4(vg[0], vg[1], vg[2], vg[3]));
        __stcs((float4*)(o_or + o), make_float4(vo[0], vo[1], vo[2], vo[3]));
        __stcs((float4*)(o_te + o), make_float4(ve[0], ve[1], ve[2], ve[3]));
    }
}

// ======================= edge (scalar, proven) =======================
__device__ __forceinline__ void body_edge(
    const float* __restrict__ imgb, float* __restrict__ out,
    int b, int x0, int y0, int tx, int ty, int tid,
    float* __restrict__ s_img,
    float* __restrict__ s_sx, float* __restrict__ s_sy, float* __restrict__ s_gm)
{
    #pragma unroll
    for (int p = 0; p < 11; p++) {
        int idx = tid + 256 * p;
        if (idx < 2800) {
            int r = idx / 40, c = idx % 40;
            int gy = y0 - 3 + r, gx = x0 - 4 + c;
            float v = 0.0f;
            if ((unsigned)gy < IH && (unsigned)gx < IW) {
                size_t o = (size_t)gy * IW + gx;
                v = imgb[o] + imgb[o + IH * IW] + imgb[o + 2 * IH * IW];
            }
            s_img[r * SIW + c] = v;
        }
    }
    __syncthreads();

    auto p2_at = [&](int r, int c) {
        const float* ip = s_img + r * SIW + (c + 1);
        float a0 = ip[0],       a1 = ip[1],           a2 = ip[2];
        float b0 = ip[SIW],                           b2 = ip[SIW + 2];
        float c0 = ip[2 * SIW], c1 = ip[2 * SIW + 1], c2 = ip[2 * SIW + 2];
        float u0 = a2 - a0, v0 = 0.5f * (a0 + a2) + a1;
        float u1 = b2 - b0;
        float u2 = c2 - c0, v2 = 0.5f * (c0 + c2) + c1;
        float sx = (0.5f * (u0 + u2) + u1) * INV3;
        float sy = (v2 - v0) * INV3;
        float gm = sqrtf(sx * sx + sy * sy);
        int gy = y0 - 2 + r, gx = x0 - 2 + c;
        if (!((unsigned)gy < IH && (unsigned)gx < IW)) { sx = 0.f; sy = 0.f; gm = 0.f; }
        s_sx[r * SW + c] = sx; s_sy[r * SW + c] = sy; s_gm[r * SW + c] = gm;
    };
    #pragma unroll
    for (int p = 0; p < 10; p++) {
        int idx = tid + 256 * p;
        if (idx < 2448) p2_at(idx / 36, idx % 36);
    }
    __syncthreads();

    float* s_t = s_img;
    auto p3_at = [&](int r, int c) {
        float sx = s_sx[(r + 1) * SW + c + 1];
        float sy = s_sy[(r + 1) * SW + c + 1];
        float gm = s_gm[(r + 1) * SW + c + 1];
        int q = quant_q(sx, sy);
        int k = q & 3;
        int dy = (k == 0) ? 0 : -1;
        int dx = 1 - (int)(k >= 2) - (int)(k == 3);
        float dp = gm - s_gm[(r + 1 + dy) * SW + c + 1 + dx];
        float dn = gm - s_gm[(r + 1 - dy) * SW + c + 1 - dx];
        float thin = (fminf(dp, dn) > 0.0f) ? gm : 0.0f;
        float t = (thin > 0.5f ? 0.5f : 0.0f) + (thin > 1.0f ? 0.5f : 0.0f);
        int gy = y0 - 1 + r, gx = x0 - 1 + c;
        if (!((unsigned)gy < IH && (unsigned)gx < IW)) t = 0.0f;
        s_t[r * SW + c] = t;
    };
    #pragma unroll
    for (int p = 0; p < 9; p++) {
        int idx = tid + 256 * p;
        if (idx < 2244) p3_at(idx / 34, idx % 34);
    }
    __syncthreads();

    const size_t plane = (size_t)NB * IH * IW;
    float* o_gx = out;
    float* o_gy = out + plane;
    float* o_gm = out + 2 * plane;
    float* o_or = out + 3 * plane;
    float* o_te = out + 4 * plane;
    {
        int r0 = 8 * ty, ix = tx;
        const float* tp = s_t + r0 * SW + ix;
        float rs0 = tp[0]  + tp[1]      + tp[2];
        float rs1 = tp[SW] + tp[SW + 1] + tp[SW + 2];
        size_t obase = (size_t)b * IH * IW + (size_t)(y0 + r0) * IW + (x0 + ix);
        #pragma unroll
        for (int j = 0; j < 8; j++) {
            const float* rp = tp + (j + 2) * SW;
            float rs2 = rp[0] + rp[1] + rp[2];
            float sum = rs0 + rs1 + rs2;
            float tc = tp[(j + 1) * SW + 1];
            int iy = r0 + j;
            float sx = s_sx[(iy + 2) * SW + ix + 2];
            float sy = s_sy[(iy + 2) * SW + ix + 2];
            float gm = s_gm[(iy + 2) * SW + ix + 2];
            int q = quant_q(sx, sy);
            float qv = (float)q * 45.0f;
            if (sx == 0.0f && sy == 0.0f) qv = __int_as_float(0x7fc00000);
            float high = (tc == 1.0f) ? 1.0f : 0.0f;
            float weak = ((sum * 1.25f > 1.0f) && (tc == 0.5f)) ? 1.0f : 0.0f;
            size_t o = obase + (size_t)j * IW;
            __stcs(o_gx + o, sx);
            __stcs(o_gy + o, sy);
            __stcs(o_gm + o, gm);
            __stcs(o_or + o, qv);
            __stcs(o_te + o, high + weak);
            rs0 = rs1; rs1 = rs2;
        }
    }
}

__global__ __launch_bounds__(256)
void canny_fused_kernel(const float* __restrict__ img, float* __restrict__ out)
{
    __shared__ float s_buf0[70 * SIW];
    __shared__ float s_sx[68 * SW + 8];   // +8 pad: P3 ld8 overreads 4 floats on last row
    __shared__ float s_sy[68 * SW + 8];
    __shared__ float s_gm[68 * SW + 8];

    const int b  = blockIdx.z;
    const int x0 = blockIdx.x * TW;
    const int y0 = blockIdx.y * TH;
    const int tx = threadIdx.x;
    const int ty = threadIdx.y;
    const int tid = ty * 32 + tx;

    const float* imgb = img + (size_t)b * 3 * IH * IW;

    const bool edge = (x0 == 0) || (y0 == 0) || (x0 + TW == IW) || (y0 + TH == IH);
    if (edge)
        body_edge(imgb, out, b, x0, y0, tx, ty, tid, s_buf0, s_sx, s_sy, s_gm);
    else
        body_int(imgb, out, b, x0, y0, tid, s_buf0, s_sx, s_sy, s_gm);
}

extern "C" void kernel_launch(void* const* d_in, const int* in_sizes, int n_in,
                              void* d_out, int out_size)
{
    const float* img = (const float*)d_in[0];
    float* out = (float*)d_out;
    dim3 block(32, 8, 1);
    dim3 grid(IW / TW, IH / TH, NB);
    canny_fused_kernel<<<grid, block>>>(img, out);
}

// round 7
// speedup vs baseline: 1.3131x; 1.3131x over previous
#include <cuda_runtime.h>
#include <cuda_bf16.h>
#include <math.h>

#define IH 1024
#define IW 1024
#define NB 8
#define TW 32
#define TH 64
#define SIW 40   // s_img row stride (floats); col c <-> gx = x0-4+c
#define SW  36   // s_gm / s_t row stride

// tan((2k+1)*pi/16)
#define T0 0.1989123673796580f
#define T1 0.6681786379192989f
#define T2 1.4966057626654890f
#define T3 5.0273394921258481f
#define INV3 0.3333333333333333f

__device__ __forceinline__ int quant_q(float sx, float sy) {
    float ax = fabsf(sx), ay = fabsf(sy);
    int mm = (int)(ay > T0 * ax) + (int)(ay > T1 * ax)
           + (int)(ay > T2 * ax) + (int)(ay > T3 * ax);
    int neg = (__float_as_int(sx) ^ __float_as_int(sy)) < 0;
    return neg ? 4 - mm : 4 + mm;
}

// sobel at gm-coord (R,C): taps s_img rows R..R+2, cols C+1..C+3 (canonical u/v form)
__device__ __forceinline__ void sobel_at(const float* __restrict__ s_img, int R, int C,
                                         float& sx, float& sy) {
    const float* ip = s_img + R * SIW + (C + 1);
    float a0 = ip[0],       a1 = ip[1],           a2 = ip[2];
    float b0 = ip[SIW],                           b2 = ip[SIW + 2];
    float c0 = ip[2 * SIW], c1 = ip[2 * SIW + 1], c2 = ip[2 * SIW + 2];
    float u0 = a2 - a0, v0 = 0.5f * (a0 + a2) + a1;
    float u1 = b2 - b0;
    float u2 = c2 - c0, v2 = 0.5f * (c0 + c2) + c1;
    sx = (0.5f * (u0 + u2) + u1) * INV3;
    sy = (v2 - v0) * INV3;
}

// NMS given center gm and 3x3 gm neighborhood rows g0,g1,g2 (center = g1[1])
__device__ __forceinline__ float nms_t(int k, float gmc,
                                       float g00, float g01, float g02,
                                       float g10,            float g12,
                                       float g20, float g21, float g22) {
    float mx0 = fmaxf(g10, g12);   // k=0: (0,±1)
    float mx1 = fmaxf(g02, g20);   // k=1: (-1,1)/(1,-1)
    float mx2 = fmaxf(g01, g21);   // k=2: (-1,0)/(1,0)
    float mx3 = fmaxf(g00, g22);   // k=3: (-1,-1)/(1,1)
    float mxa = (k & 1) ? mx1 : mx0;
    float mxb = (k & 1) ? mx3 : mx2;
    float mx  = (k & 2) ? mxb : mxa;
    float thin = (gmc > mx) ? gmc : 0.0f;
    return (thin > 0.5f ? 0.5f : 0.0f) + (thin > 1.0f ? 0.5f : 0.0f);
}

template<bool EDGE>
__device__ __forceinline__ void body(
    const float* __restrict__ imgb, float* __restrict__ out,
    int b, int x0, int y0, int tx, int ty, int tid,
    float* __restrict__ s_img, float* __restrict__ s_gm, float* __restrict__ s_t)
{
    // ---- P1: channel-summed image, rows 0..69 (gy=y0-3+r) x cols 0..39 (gx=x0-4+c)
    if (!EDGE) {
        const float4* base = (const float4*)(imgb + (size_t)(y0 - 3) * IW + (x0 - 4));
        const int CH4 = IH * IW / 4;
        #pragma unroll
        for (int p = 0; p < 3; p++) {
            int idx = tid + 256 * p;
            if (idx < 700) {
                int r = idx / 10, c4 = idx % 10;
                const float4* ptr = base + r * (IW / 4) + c4;
                float4 v0 = ptr[0], v1 = ptr[CH4], v2 = ptr[2 * CH4];
                float4 s;
                s.x = v0.x + v1.x + v2.x; s.y = v0.y + v1.y + v2.y;
                s.z = v0.z + v1.z + v2.z; s.w = v0.w + v1.w + v2.w;
                *(float4*)&s_img[r * SIW + c4 * 4] = s;
            }
        }
    } else {
        #pragma unroll
        for (int p = 0; p < 11; p++) {
            int idx = tid + 256 * p;
            if (idx < 2800) {
                int r = idx / 40, c = idx % 40;
                int gy = y0 - 3 + r, gx = x0 - 4 + c;
                float v = 0.0f;
                if ((unsigned)gy < IH && (unsigned)gx < IW) {
                    size_t o = (size_t)gy * IW + gx;
                    v = imgb[o] + imgb[o + IH * IW] + imgb[o + 2 * IH * IW];
                }
                s_img[r * SIW + c] = v;
            }
        }
    }
    __syncthreads();

    // ---- P2: gm only. gm row r <-> gy=y0-2+r (0..67), col c <-> gx=x0-2+c (0..35)
    auto p2_at = [&](int r, int c) {
        float sx, sy;
        sobel_at(s_img, r, c, sx, sy);
        float gm = sqrtf(sx * sx + sy * sy);
        if (EDGE) {
            int gy = y0 - 2 + r, gx = x0 - 2 + c;
            if (!((unsigned)gy < IH && (unsigned)gx < IW)) gm = 0.f;
        }
        s_gm[r * SW + c] = gm;
    };
    {   // main rolling: rows 2..65, cols 0..31
        int r0 = 2 + 8 * ty, c = tx;
        const float* ip = s_img + r0 * SIW + (c + 1);
        float a0 = ip[0], a1 = ip[1], a2 = ip[2];
        float u0 = a2 - a0, v0 = 0.5f * (a0 + a2) + a1;
        float b0 = ip[SIW], b1 = ip[SIW + 1], b2 = ip[SIW + 2];
        float u1 = b2 - b0, v1 = 0.5f * (b0 + b2) + b1;
        #pragma unroll
        for (int j = 0; j < 8; j++) {
            const float* rp = ip + (j + 2) * SIW;
            float c0 = rp[0], c1 = rp[1], c2 = rp[2];
            float u2 = c2 - c0, v2 = 0.5f * (c0 + c2) + c1;
            float sx = (0.5f * (u0 + u2) + u1) * INV3;
            float sy = (v2 - v0) * INV3;
            float gm = sqrtf(sx * sx + sy * sy);
            int r = r0 + j;
            if (EDGE) {
                int gy = y0 - 2 + r, gx = x0 - 2 + c;
                if (!((unsigned)gy < IH && (unsigned)gx < IW)) gm = 0.f;
            }
            s_gm[r * SW + c] = gm;
            u0 = u1; u1 = u2; v0 = v1; v1 = v2;
        }
    }
    if (tid < 144) {            // tail A: rows {0,1,66,67} x cols 0..35
        int rr = tid / 36, c = tid % 36;
        p2_at((rr < 2) ? rr : 64 + rr, c);
    }
    {                           // tail B: rows 2..65 x cols 32..35 (exactly 256)
        p2_at(2 + (tid >> 2), 32 + (tid & 3));
    }
    __syncthreads();

    // ---- P3: quant + NMS -> t. t row r <-> gy=y0-1+r (0..65), col c <-> gx=x0-1+c (0..33)
    // center gm at (r+1,c+1); sobel recompute at gm-coord (r+1,c+1)
    auto p3_at = [&](int r, int c) {
        float sx, sy;
        sobel_at(s_img, r + 1, c + 1, sx, sy);
        const float* gp = s_gm + r * SW + c;
        float gmc = gp[SW + 1];
        int k = quant_q(sx, sy) & 3;
        float t = nms_t(k, gmc, gp[0], gp[1], gp[2], gp[SW], gp[SW + 2],
                        gp[2 * SW], gp[2 * SW + 1], gp[2 * SW + 2]);
        if (EDGE) {
            int gy = y0 - 1 + r, gx = x0 - 1 + c;
            if (!((unsigned)gy < IH && (unsigned)gx < IW)) t = 0.0f;
        }
        s_t[r * SW + c] = t;
    };
    {   // main rolling: rows 1..64, cols 0..31
        int r0 = 1 + 8 * ty, c = tx;
        const float* gp = s_gm + r0 * SW + c;
        float gA0 = gp[0],  gA1 = gp[1],      gA2 = gp[2];
        float gB0 = gp[SW], gB1 = gp[SW + 1], gB2 = gp[SW + 2];
        // img rolling for sobel at (r+1, c+1): taps rows r+1..r+3, cols c+2..c+4
        const float* ip = s_img + (r0 + 1) * SIW + (c + 2);
        float a0 = ip[0], a1 = ip[1], a2 = ip[2];
        float u0 = a2 - a0, v0 = 0.5f * (a0 + a2) + a1;
        float b0 = ip[SIW], b1 = ip[SIW + 1], b2 = ip[SIW + 2];
        float u1 = b2 - b0, v1 = 0.5f * (b0 + b2) + b1;
        #pragma unroll
        for (int j = 0; j < 8; j++) {
            int r = r0 + j;
            const float* gq = s_gm + (r + 2) * SW + c;
            float gC0 = gq[0], gC1 = gq[1], gC2 = gq[2];
            const float* rp = ip + (j + 2) * SIW;
            float c0 = rp[0], c1 = rp[1], c2 = rp[2];
            float u2 = c2 - c0, v2 = 0.5f * (c0 + c2) + c1;
            float sx = (0.5f * (u0 + u2) + u1) * INV3;
            float sy = (v2 - v0) * INV3;
            int k = quant_q(sx, sy) & 3;
            float t = nms_t(k, gB1, gA0, gA1, gA2, gB0, gB2, gC0, gC1, gC2);
            if (EDGE) {
                int gy = y0 - 1 + r, gx = x0 - 1 + c;
                if (!((unsigned)gy < IH && (unsigned)gx < IW)) t = 0.0f;
            }
            s_t[r * SW + c] = t;
            gA0 = gB0; gA1 = gB1; gA2 = gB2;
            gB0 = gC0; gB1 = gC1; gB2 = gC2;
            u0 = u1; u1 = u2; v0 = v1; v1 = v2;
        }
    }
    if (tid < 68) {             // tail A: rows {0,65} x cols 0..33
        int rr = tid / 34, c = tid % 34;
        p3_at(rr ? 65 : 0, c);
    } else if (tid < 196) {     // tail B: rows 1..64 x cols 32..33
        int k2 = tid - 68;
        p3_at(1 + (k2 >> 1), 32 + (k2 & 1));
    }
    __syncthreads();

    // ---- P4: hysteresis + 5-plane output (64x32 center) ----
    const size_t plane = (size_t)NB * IH * IW;
    float* o_gx = out;
    float* o_gy = out + plane;
    float* o_gm = out + 2 * plane;
    float* o_or = out + 3 * plane;
    float* o_te = out + 4 * plane;
    {
        int r0 = 8 * ty, ix = tx;
        const float* tp = s_t + r0 * SW + ix;
        float rs0 = tp[0]  + tp[1]      + tp[2];
        float rs1 = tp[SW] + tp[SW + 1] + tp[SW + 2];
        // img rolling for sobel at gm-coord (iy+2, ix+2): rows iy+2..iy+4, cols ix+3..ix+5
        const float* ip = s_img + (r0 + 2) * SIW + (ix + 3);
        float a0 = ip[0], a1 = ip[1], a2 = ip[2];
        float u0 = a2 - a0, v0 = 0.5f * (a0 + a2) + a1;
        float b0 = ip[SIW], b1 = ip[SIW + 1], b2 = ip[SIW + 2];
        float u1 = b2 - b0, v1 = 0.5f * (b0 + b2) + b1;
        size_t obase = (size_t)b * IH * IW + (size_t)(y0 + r0) * IW + (x0 + ix);
        #pragma unroll
        for (int j = 0; j < 8; j++) {
            int iy = r0 + j;
            const float* rp2 = tp + (j + 2) * SW;
            float rs2 = rp2[0] + rp2[1] + rp2[2];
            float sum = rs0 + rs1 + rs2;
            float tc = tp[(j + 1) * SW + 1];
            const float* rp = ip + (j + 2) * SIW;
            float c0 = rp[0], c1 = rp[1], c2 = rp[2];
            float u2 = c2 - c0, v2 = 0.5f * (c0 + c2) + c1;
            float sx = (0.5f * (u0 + u2) + u1) * INV3;
            float sy = (v2 - v0) * INV3;
            float gm = s_gm[(iy + 2) * SW + ix + 2];
            int q = quant_q(sx, sy);
            float qv = (float)q * 45.0f;
            if (sx == 0.0f && sy == 0.0f) qv = __int_as_float(0x7fc00000);
            float high = (tc == 1.0f) ? 1.0f : 0.0f;
            float weak = ((sum * 1.25f > 1.0f) && (tc == 0.5f)) ? 1.0f : 0.0f;
            size_t o = obase + (size_t)j * IW;
            __stcs(o_gx + o, sx);
            __stcs(o_gy + o, sy);
            __stcs(o_gm + o, gm);
            __stcs(o_or + o, qv);
            __stcs(o_te + o, high + weak);
            rs0 = rs1; rs1 = rs2;
            u0 = u1; u1 = u2; v0 = v1; v1 = v2;
        }
    }
}

__global__ __launch_bounds__(256, 6)
void canny_fused_kernel(const float* __restrict__ img, float* __restrict__ out)
{
    __shared__ float s_img[70 * SIW];        // 2800 floats
    __shared__ float s_gm [68 * SW + 8];     // 2456
    __shared__ float s_t  [66 * SW + 8];     // 2384   (total ~30.6 KB)

    const int b  = blockIdx.z;
    const int x0 = blockIdx.x * TW;
    const int y0 = blockIdx.y * TH;
    const int tx = threadIdx.x;
    const int ty = threadIdx.y;
    const int tid = ty * 32 + tx;

    const float* imgb = img + (size_t)b * 3 * IH * IW;

    const bool edge = (x0 == 0) || (y0 == 0) || (x0 + TW == IW) || (y0 + TH == IH);
    if (edge)
        body<true >(imgb, out, b, x0, y0, tx, ty, tid, s_img, s_gm, s_t);
    else
        body<false>(imgb, out, b, x0, y0, tx, ty, tid, s_img, s_gm, s_t);
}

extern "C" void kernel_launch(void* const* d_in, const int* in_sizes, int n_in,
                              void* d_out, int out_size)
{
    const float* img = (const float*)d_in[0];
    float* out = (float*)d_out;
    dim3 block(32, 8, 1);
    dim3 grid(IW / TW, IH / TH, NB);
    canny_fused_kernel<<<grid, block>>>(img, out);
}